// round 15
// baseline (speedup 1.0000x reference)
#include <cuda_runtime.h>
#include <cuda_fp16.h>
#include <cstdint>

#define NBLK   128
#define GRP    64
#define NTHR   256
#define TSTEPS 512
#define OUTN   (512*128*512)

// ---- smem byte offsets -----------------------------------------------------
#define SM_BIAS 0          // 32 f32
#define SM_ZSHX 128        // 32*132*4 = 16896
#define SM_ZSHH 17024      // 16896
#define SM_W    33920      // B frags: [64 sg][4 nt][32 lane]*8B = 65536
#define SM_A    99456      // 2 groups * 4 bufs * 16KB = 131072
#define SM_TOT  230528

// ---- persistent state ------------------------------------------------------
__device__ __align__(16) __half g_x[(size_t)TSTEPS*128*512];
__device__ __align__(16) __half g_hst[2][2][128*512];   // [layer][pingpong]
__device__ __align__(16) __half g_mid[2][128*512];      // [pingpong]
__device__ unsigned g_bar_count;
__device__ volatile unsigned g_bar_gen;
__device__ __align__(256) unsigned g_flagM[GRP];    // L0 CTA g done step t => t+1
__device__ __align__(256) unsigned g_flagL1[GRP];   // L1 CTA g done step t => t+1

// ---- reset kernel (graph-replay-safe) --------------------------------------
__global__ void reset_flags() {
    g_bar_count = 0; g_bar_gen = 0;
    for (int i = 0; i < GRP; ++i) { g_flagM[i] = 0; g_flagL1[i] = 0; }
}

// ---- full 128-CTA barrier (once, after init) -------------------------------
__device__ __forceinline__ void grid_barrier_full() {
    __syncthreads();
    if (threadIdx.x == 0) {
        __threadfence();
        unsigned gen = g_bar_gen;
        if (atomicAdd(&g_bar_count, 1u) == NBLK - 1) {
            g_bar_count = 0;
            __threadfence();
            g_bar_gen = gen + 1;
        } else {
            while (g_bar_gen == gen) { __nanosleep(20); }
        }
        __threadfence();
    }
    __syncthreads();
}

// ---- flag ops ---------------------------------------------------------------
__device__ __forceinline__ unsigned ld_acq(const unsigned* p) {
    unsigned v;
    asm volatile("ld.acquire.gpu.b32 %0, [%1];" : "=r"(v) : "l"(p) : "memory");
    return v;
}
__device__ __forceinline__ void st_rel(unsigned* p, unsigned v) {
    asm volatile("st.release.gpu.b32 [%0], %1;" :: "l"(p), "r"(v) : "memory");
}
__device__ __forceinline__ void barn(int id) {
    asm volatile("bar.sync %0, 128;" :: "r"(id) : "memory");
}
// group-local wait: 64 of the group's 128 threads poll 64 slots in parallel
__device__ __forceinline__ void wait_flags_grp(unsigned* flags, int target,
                                               int gtid, int barid) {
    if (target > 0 && gtid < GRP) {
        while ((int)ld_acq(flags + gtid) < target) { __nanosleep(20); }
    }
    barn(barid);
}

// ---- asm helpers -----------------------------------------------------------
__device__ __forceinline__ void cp16(uint32_t s, const void* g) {
    asm volatile("cp.async.cg.shared.global [%0], [%1], 16;" :: "r"(s), "l"(g));
}
__device__ __forceinline__ void cp_commit() { asm volatile("cp.async.commit_group;"); }
template<int N> __device__ __forceinline__ void cp_wait() {
    asm volatile("cp.async.wait_group %0;" :: "n"(N));
}
__device__ __forceinline__ void ldm4(uint32_t (&a)[4], uint32_t addr) {
    asm volatile("ldmatrix.sync.aligned.m8n8.x4.shared.b16 {%0,%1,%2,%3}, [%4];"
                 : "=r"(a[0]), "=r"(a[1]), "=r"(a[2]), "=r"(a[3]) : "r"(addr));
}
__device__ __forceinline__ void mma(float (&d)[4], const uint32_t (&a)[4],
                                    uint32_t b0, uint32_t b1) {
    asm volatile("mma.sync.aligned.m16n8k16.row.col.f32.f16.f16.f32 "
        "{%0,%1,%2,%3}, {%4,%5,%6,%7}, {%8,%9}, {%0,%1,%2,%3};"
        : "+f"(d[0]), "+f"(d[1]), "+f"(d[2]), "+f"(d[3])
        : "r"(a[0]), "r"(a[1]), "r"(a[2]), "r"(a[3]), "r"(b0), "r"(b1));
}
__device__ __forceinline__ void stcg4v(void* p, uint32_t a, uint32_t b,
                                       uint32_t c, uint32_t d) {
    asm volatile("st.global.cg.v4.b32 [%0], {%1,%2,%3,%4};"
                 :: "l"(p), "r"(a), "r"(b), "r"(c), "r"(d));
}
__device__ __forceinline__ void stcg16(void* p, unsigned short v) {
    asm volatile("st.global.cg.u16 [%0], %1;" :: "l"(p), "h"(v));
}

__device__ __forceinline__ float sigm(float x) { return 1.0f / (1.0f + __expf(-x)); }

// ---- A staging: group-warp wg stages its 32-row band of k-chunk kc ---------
__device__ __forceinline__ void stage32(const __half* src, int kc, int buf,
                                        uint32_t ringbase, int wg, int lane) {
    int coff = (kc & 7) << 6;
    uint32_t dst = ringbase + buf * 16384;
    int rq = lane >> 3, cq = lane & 7;
#pragma unroll
    for (int jj = 0; jj < 8; ++jj) {
        int row = wg * 32 + jj * 4 + rq;
        uint32_t d = dst + row * 128 + ((cq ^ (row & 7)) << 4);
        cp16(d, src + (size_t)row * 512 + coff + cq * 8);
    }
}

// ---- per-chunk GEMM: 4 ks x 4 nt x 2 mt = 32 HMMA --------------------------
__device__ __forceinline__ void chunk_mma(int kc, int buf, uint32_t ringbase,
                                          const uint2* bf, int wg, int lane,
                                          float (&acc)[2][4][4]) {
    int sub = lane >> 3, lrow = lane & 7;
    uint32_t ab = ringbase + buf * 16384;
#pragma unroll
    for (int ks = 0; ks < 4; ++ks) {
        uint32_t Ah[2][4];
#pragma unroll
        for (int mt = 0; mt < 2; ++mt) {
            int r = wg * 32 + mt * 16 + ((sub & 1) << 3) + lrow;
            uint32_t aoff = r * 128 + (((2 * ks + (sub >> 1)) ^ (r & 7)) << 4);
            ldm4(Ah[mt], ab + aoff);
        }
        int sg = kc * 4 + ks;
#pragma unroll
        for (int nt = 0; nt < 4; ++nt) {
            uint2 Bh = bf[(sg * 4 + nt) * 32 + lane];
#pragma unroll
            for (int mt = 0; mt < 2; ++mt)
                mma(acc[mt][nt], Ah[mt], Bh.x, Bh.y);
        }
    }
}

// ---- one half: 8 chunks, 4-deep warp-private ring --------------------------
__device__ __forceinline__ void run_half(const __half* src, int kcbase,
                                         uint32_t ringbase, const uint2* bf,
                                         int wg, int lane, float (&acc)[2][4][4]) {
#pragma unroll
    for (int c = 0; c < 4; ++c) { stage32(src, kcbase + c, c, ringbase, wg, lane); cp_commit(); }
#pragma unroll 1
    for (int i = 0; i < 8; ++i) {
        cp_wait<3>();
        chunk_mma(kcbase + i, i & 3, ringbase, bf, wg, lane, acc);
        if (i < 4) stage32(src, kcbase + i + 4, i & 3, ringbase, wg, lane);
        cp_commit();
    }
}

// ---- z partial -> smem ------------------------------------------------------
__device__ __forceinline__ void store_z(float* zsh, float (&acc)[2][4][4],
                                        int wg, int lane) {
#pragma unroll
    for (int mt = 0; mt < 2; ++mt)
#pragma unroll
        for (int nt = 0; nt < 4; ++nt) {
            int m0 = wg * 32 + mt * 16 + (lane >> 2);
            int n0 = nt * 8 + (lane & 3) * 2;
            zsh[n0 * 132 + m0]           = acc[mt][nt][0];
            zsh[(n0 + 1) * 132 + m0]     = acc[mt][nt][1];
            zsh[n0 * 132 + m0 + 8]       = acc[mt][nt][2];
            zsh[(n0 + 1) * 132 + m0 + 8] = acc[mt][nt][3];
        }
}

// ---- main persistent kernel ------------------------------------------------
__global__ void __launch_bounds__(NTHR, 1) lstm_tc(
    const float* __restrict__ hxs, const float* __restrict__ masks,
    const float* __restrict__ W_ih, const float* __restrict__ W_hh,
    const float* __restrict__ b_ih, const float* __restrict__ b_hh,
    float* __restrict__ out)
{
    extern __shared__ __align__(1024) char sm[];
    uint32_t smb = (uint32_t)__cvta_generic_to_shared(sm);
    int tid = threadIdx.x, blk = blockIdx.x, w = tid >> 5, lane = tid & 31;
    int isL0 = (blk < GRP);
    int g = isL0 ? blk : (blk - GRP);
    int l = isL0 ? 0 : 1;
    int isX = (w < 4);           // warp group X: warps 0-3; H: warps 4-7
    int wg = w & 3;              // group-local warp id
    uint32_t ringX = smb + SM_A;
    uint32_t ringH = smb + SM_A + 65536;

    // ---- weight conversion: this CTA's 32 gate cols, K=1024, plain fp16 ----
    unsigned short* bw = (unsigned short*)(sm + SM_W);
    for (int idx = tid; idx < 32 * 1024; idx += NTHR) {
        int col = idx >> 10, k = idx & 1023;
        int grow = (col >> 3) * 512 + g * 8 + (col & 7);
        float wv = (k < 512)
            ? W_ih[((size_t)l * 2048 + grow) * 512 + k]
            : W_hh[((size_t)l * 2048 + grow) * 512 + (k - 512)];
        unsigned short hi = __half_as_ushort(__float2half_rn(wv));
        int sg = k >> 4, kk = k & 15;
        int reg = (kk >> 3) & 1, pos = kk & 1;
        int lamd = (col & 7) * 4 + ((kk & 7) >> 1);
        int nt = col >> 3;
        bw[(sg * 4 + nt) * 128 + lamd * 4 + reg * 2 + pos] = hi;
    }
    if (tid < 32) {
        int c = tid;
        int grow = (c >> 3) * 512 + g * 8 + (c & 7);
        ((float*)(sm + SM_BIAS))[c] = b_ih[l * 2048 + grow] + b_hh[l * 2048 + grow];
    }

    // ---- init masked h state (pp=0): grid-strided over both layers ---------
    for (int idx = blk * NTHR + tid; idx < 2 * 65536; idx += NBLK * NTHR) {
        int ll = idx >> 16, r = idx & 65535;
        int n = r >> 9, jj = r & 511;
        float v = hxs[(size_t)ll * 131072 + n * 1024 + jj] * __ldg(masks + n);
        stcg16(&g_hst[ll][0][r], __half_as_ushort(__float2half_rn(v)));
    }
    // c-state lives in threads 0-127 (n = tid), 8 units each
    float creg[8];
    if (tid < 128) {
#pragma unroll
        for (int u = 0; u < 8; ++u)
            creg[u] = hxs[(size_t)l * 131072 + tid * 1024 + 512 + g * 8 + u];
    }

    grid_barrier_full();
    const uint2* bf = (const uint2*)(sm + SM_W);
    float* zshx = (float*)(sm + SM_ZSHX);
    float* zshh = (float*)(sm + SM_ZSHH);
    const float* bs = (const float*)(sm + SM_BIAS);

#pragma unroll 1
    for (int t = 0; t < TSTEPS; ++t) {
        int pr = t & 1, pw = pr ^ 1, mb = t & 1;
        float acc[2][4][4] = {};

        if (isX) {
            // X group: dependency-light half (k 0..511)
            if (isL0) {
                run_half(g_x + (size_t)t * 65536, 0, ringX, bf, wg, lane, acc);
            } else {
                // L1 mid-half: needs all L0 done step t
                wait_flags_grp(g_flagM, t + 1, tid, 2);
                run_half(g_mid[mb], 0, ringX, bf, wg, lane, acc);
            }
            store_z(zshx, acc, wg, lane);
        } else {
            // H group: recurrent half (k 512..1023)
            if (isL0) {
                wait_flags_grp(g_flagM, t, tid - 128, 1);
                wait_flags_grp(g_flagL1, t - 1, tid - 128, 1);
                run_half(g_hst[0][pr], 8, ringH, bf, wg, lane, acc);
            } else {
                wait_flags_grp(g_flagL1, t, tid - 128, 1);
                run_half(g_hst[1][pr], 8, ringH, bf, wg, lane, acc);
            }
            store_z(zshh, acc, wg, lane);
        }
        __syncthreads();

        // ---- gates: threads 0-127 (own creg), combine both partials ---------
        if (tid < 128) {
            int n = tid;
            float m  = __ldg(masks + t * 128 + n);
            float mn = (t < TSTEPS - 1) ? __ldg(masks + (t + 1) * 128 + n) : 0.f;
            unsigned short sh[8], th[8];
            float hv[8];
#pragma unroll
            for (int u = 0; u < 8; ++u) {
                float zi = zshx[(0  + u) * 132 + n] + zshh[(0  + u) * 132 + n] + bs[u];
                float zf = zshx[(8  + u) * 132 + n] + zshh[(8  + u) * 132 + n] + bs[8 + u];
                float zg = zshx[(16 + u) * 132 + n] + zshh[(16 + u) * 132 + n] + bs[16 + u];
                float zo = zshx[(24 + u) * 132 + n] + zshh[(24 + u) * 132 + n] + bs[24 + u];
                float ii = sigm(zi), ff = sigm(zf), oo = sigm(zo);
                float gg = tanhf(zg);
                float cc = ff * (creg[u] * m) + ii * gg;
                float hh = oo * tanhf(cc);
                creg[u] = cc;
                hv[u] = hh;
                sh[u] = __half_as_ushort(__float2half_rn(hh * mn));
                if (isL0) th[u] = __half_as_ushort(__float2half_rn(hh));
            }
            size_t base = (size_t)n * 512 + g * 8;
            stcg4v(&g_hst[l][pw][base],
                   sh[0] | ((uint32_t)sh[1] << 16), sh[2] | ((uint32_t)sh[3] << 16),
                   sh[4] | ((uint32_t)sh[5] << 16), sh[6] | ((uint32_t)sh[7] << 16));
            if (isL0) {
                stcg4v(&g_mid[mb][base],
                       th[0] | ((uint32_t)th[1] << 16), th[2] | ((uint32_t)th[3] << 16),
                       th[4] | ((uint32_t)th[5] << 16), th[6] | ((uint32_t)th[7] << 16));
            } else {
                float* op = out + (size_t)t * 65536 + base;
                *(float4*)op       = make_float4(hv[0], hv[1], hv[2], hv[3]);
                *(float4*)(op + 4) = make_float4(hv[4], hv[5], hv[6], hv[7]);
            }
            if (t == TSTEPS - 1) {
#pragma unroll
                for (int u = 0; u < 8; ++u) {
                    out[OUTN + l * 131072 + n * 1024 + g * 8 + u]       = hv[u];
                    out[OUTN + l * 131072 + n * 1024 + 512 + g * 8 + u] = creg[u];
                }
            }
        }
        __syncthreads();   // zsh reusable; all state writes issued

        if (tid == 0) {
            __threadfence();
            if (isL0) st_rel(&g_flagM[g],  (unsigned)(t + 1));
            else      st_rel(&g_flagL1[g], (unsigned)(t + 1));
        }
    }
}

// ---- x -> fp16 -------------------------------------------------------------
__global__ void __launch_bounds__(256) xconv(const float* __restrict__ x) {
    size_t i = (size_t)blockIdx.x * 256 + threadIdx.x;
    if (i >= (size_t)OUTN / 4) return;
    float4 v = __ldg(((const float4*)x) + i);
    unsigned short h0 = __half_as_ushort(__float2half_rn(v.x));
    unsigned short h1 = __half_as_ushort(__float2half_rn(v.y));
    unsigned short h2 = __half_as_ushort(__float2half_rn(v.z));
    unsigned short h3 = __half_as_ushort(__float2half_rn(v.w));
    *(uint2*)(g_x + i * 4) = make_uint2(h0 | ((uint32_t)h1 << 16),
                                        h2 | ((uint32_t)h3 << 16));
}

// ---- LayerNorm -------------------------------------------------------------
__global__ void __launch_bounds__(256) ln_kernel(float* __restrict__ out,
                                                 const float* __restrict__ gamma,
                                                 const float* __restrict__ beta)
{
    int lane = threadIdx.x & 31;
    int row  = blockIdx.x * 8 + (threadIdx.x >> 5);
    float* p = out + (size_t)row * 512;
    float4 v[4];
    float s = 0.f, sq = 0.f;
#pragma unroll
    for (int k = 0; k < 4; ++k) {
        v[k] = ((const float4*)p)[(k << 5) + lane];
        s += v[k].x + v[k].y + v[k].z + v[k].w;
        sq = fmaf(v[k].x, v[k].x, sq); sq = fmaf(v[k].y, v[k].y, sq);
        sq = fmaf(v[k].z, v[k].z, sq); sq = fmaf(v[k].w, v[k].w, sq);
    }
#pragma unroll
    for (int o = 16; o; o >>= 1) {
        s  += __shfl_xor_sync(0xffffffffu, s,  o);
        sq += __shfl_xor_sync(0xffffffffu, sq, o);
    }
    float mean = s * (1.0f / 512.0f);
    float inv  = rsqrtf(sq * (1.0f / 512.0f) - mean * mean + 1e-5f);
#pragma unroll
    for (int k = 0; k < 4; ++k) {
        float4 gm = ((const float4*)gamma)[(k << 5) + lane];
        float4 bt = ((const float4*)beta)[(k << 5) + lane];
        float4 r;
        r.x = (v[k].x - mean) * inv * gm.x + bt.x;
        r.y = (v[k].y - mean) * inv * gm.y + bt.y;
        r.z = (v[k].z - mean) * inv * gm.z + bt.z;
        r.w = (v[k].w - mean) * inv * gm.w + bt.w;
        ((float4*)p)[(k << 5) + lane] = r;
    }
}

// ---------------------------------------------------------------------------
extern "C" void kernel_launch(void* const* d_in, const int* in_sizes, int n_in,
                              void* d_out, int out_size) {
    const float* x     = (const float*)d_in[0];
    const float* hxs   = (const float*)d_in[1];
    const float* masks = (const float*)d_in[2];
    const float* W_ih  = (const float*)d_in[3];
    const float* W_hh  = (const float*)d_in[4];
    const float* b_ih  = (const float*)d_in[5];
    const float* b_hh  = (const float*)d_in[6];
    const float* gamma = (const float*)d_in[7];
    const float* beta  = (const float*)d_in[8];
    float* out = (float*)d_out;

    cudaFuncSetAttribute(lstm_tc, cudaFuncAttributeMaxDynamicSharedMemorySize, SM_TOT);

    reset_flags<<<1, 1>>>();
    xconv<<<(OUTN / 4 + 255) / 256, 256>>>(x);
    lstm_tc<<<NBLK, NTHR, SM_TOT>>>(hxs, masks, W_ih, W_hh, b_ih, b_hh, out);
    ln_kernel<<<65536 / 8, 256>>>(out, gamma, beta);
}

// round 17
// speedup vs baseline: 1.3297x; 1.3297x over previous
#include <cuda_runtime.h>
#include <cuda_fp16.h>
#include <cstdint>

#define NBLK   128
#define GRP    64
#define NTHR   128
#define TSTEPS 512
#define OUTN   (512*128*512)

// ---- smem byte offsets -----------------------------------------------------
#define SM_W    0          // B frags: [64 sg][4 nt][32 lane]*8B = 65536
#define SM_A    65536      // 8 bufs * 16KB = 131072
#define SM_TOT  196608

// ---- persistent state ------------------------------------------------------
__device__ __align__(16) __half g_x[(size_t)TSTEPS*128*512];
__device__ __align__(16) __half g_hst[2][2][128*512];   // [layer][pingpong]
__device__ __align__(16) __half g_mid[2][128*512];      // [pingpong]
__device__ unsigned g_bar_count;
__device__ volatile unsigned g_bar_gen;
__device__ __align__(256) unsigned g_flagM[GRP];    // L0 CTA g done step t => t+1
__device__ __align__(256) unsigned g_flagL1[GRP];   // L1 CTA g done step t => t+1

// ---- reset kernel (graph-replay-safe) --------------------------------------
__global__ void reset_flags() {
    g_bar_count = 0; g_bar_gen = 0;
    for (int i = 0; i < GRP; ++i) { g_flagM[i] = 0; g_flagL1[i] = 0; }
}

// ---- full 128-CTA barrier (once, after init) -------------------------------
__device__ __forceinline__ void grid_barrier_full() {
    __syncthreads();
    if (threadIdx.x == 0) {
        __threadfence();
        unsigned gen = g_bar_gen;
        if (atomicAdd(&g_bar_count, 1u) == NBLK - 1) {
            g_bar_count = 0;
            __threadfence();
            g_bar_gen = gen + 1;
        } else {
            while (g_bar_gen == gen) { __nanosleep(20); }
        }
        __threadfence();
    }
    __syncthreads();
}

// ---- flag ops ---------------------------------------------------------------
__device__ __forceinline__ unsigned ld_acq(const unsigned* p) {
    unsigned v;
    asm volatile("ld.acquire.gpu.b32 %0, [%1];" : "=r"(v) : "l"(p) : "memory");
    return v;
}
__device__ __forceinline__ void st_rel(unsigned* p, unsigned v) {
    asm volatile("st.release.gpu.b32 [%0], %1;" :: "l"(p), "r"(v) : "memory");
}
// all threads call; 64 threads poll 64 slots in parallel, then block-sync
__device__ __forceinline__ void wait_flags(unsigned* flags, int target) {
    if (target > 0 && (int)threadIdx.x < GRP) {
        while ((int)ld_acq(flags + threadIdx.x) < target) { __nanosleep(20); }
    }
    __syncthreads();
}

// ---- asm helpers -----------------------------------------------------------
__device__ __forceinline__ void cp16(uint32_t s, const void* g) {
    asm volatile("cp.async.cg.shared.global [%0], [%1], 16;" :: "r"(s), "l"(g));
}
__device__ __forceinline__ void cp_commit() { asm volatile("cp.async.commit_group;"); }
template<int N> __device__ __forceinline__ void cp_wait() {
    asm volatile("cp.async.wait_group %0;" :: "n"(N));
}
__device__ __forceinline__ void ldm4(uint32_t (&a)[4], uint32_t addr) {
    asm volatile("ldmatrix.sync.aligned.m8n8.x4.shared.b16 {%0,%1,%2,%3}, [%4];"
                 : "=r"(a[0]), "=r"(a[1]), "=r"(a[2]), "=r"(a[3]) : "r"(addr));
}
__device__ __forceinline__ void mma(float (&d)[4], const uint32_t (&a)[4],
                                    uint32_t b0, uint32_t b1) {
    asm volatile("mma.sync.aligned.m16n8k16.row.col.f32.f16.f16.f32 "
        "{%0,%1,%2,%3}, {%4,%5,%6,%7}, {%8,%9}, {%0,%1,%2,%3};"
        : "+f"(d[0]), "+f"(d[1]), "+f"(d[2]), "+f"(d[3])
        : "r"(a[0]), "r"(a[1]), "r"(a[2]), "r"(a[3]), "r"(b0), "r"(b1));
}
__device__ __forceinline__ void stcg4(void* p, uint32_t a) {
    asm volatile("st.global.cg.b32 [%0], %1;" :: "l"(p), "r"(a));
}
__device__ __forceinline__ void stcg16(void* p, unsigned short v) {
    asm volatile("st.global.cg.u16 [%0], %1;" :: "l"(p), "h"(v));
}

__device__ __forceinline__ float sigm(float x) { return 1.0f / (1.0f + __expf(-x)); }

// ---- A staging: warp w stages its 32-row band of k-chunk kc into buf -------
__device__ __forceinline__ void stage32(const __half* src, int kc, int buf,
                                        uint32_t abase, int w, int lane) {
    int coff = (kc & 7) << 6;
    uint32_t dst = abase + buf * 16384;
    int rq = lane >> 3, cq = lane & 7;
#pragma unroll
    for (int jj = 0; jj < 8; ++jj) {
        int row = w * 32 + jj * 4 + rq;
        uint32_t d = dst + row * 128 + ((cq ^ (row & 7)) << 4);
        cp16(d, src + (size_t)row * 512 + coff + cq * 8);
    }
}

// ---- per-chunk GEMM: 4 ks x 4 nt x 2 mt = 32 HMMA --------------------------
__device__ __forceinline__ void chunk_mma(int kc, int buf, uint32_t abase,
                                          const uint2* bf, int w, int lane,
                                          float (&acc)[2][4][4]) {
    int sub = lane >> 3, lrow = lane & 7;
    uint32_t ab = abase + buf * 16384;
#pragma unroll
    for (int ks = 0; ks < 4; ++ks) {
        uint32_t Ah[2][4];
#pragma unroll
        for (int mt = 0; mt < 2; ++mt) {
            int r = w * 32 + mt * 16 + ((sub & 1) << 3) + lrow;
            uint32_t aoff = r * 128 + (((2 * ks + (sub >> 1)) ^ (r & 7)) << 4);
            ldm4(Ah[mt], ab + aoff);
        }
        int sg = kc * 4 + ks;
#pragma unroll
        for (int nt = 0; nt < 4; ++nt) {
            uint2 Bh = bf[(sg * 4 + nt) * 32 + lane];
#pragma unroll
            for (int mt = 0; mt < 2; ++mt)
                mma(acc[mt][nt], Ah[mt], Bh.x, Bh.y);
        }
    }
}

// ---- whole-half: stage all 8 chunks upfront, then compute -------------------
template<int CB>
__device__ __forceinline__ void half8(const __half* src, uint32_t abase,
                                      const uint2* bf, int w, int lane,
                                      float (&acc)[2][4][4]) {
#pragma unroll
    for (int i = 0; i < 8; ++i) { stage32(src, CB + i, i, abase, w, lane); cp_commit(); }
    cp_wait<7>(); chunk_mma(CB + 0, 0, abase, bf, w, lane, acc);
    cp_wait<6>(); chunk_mma(CB + 1, 1, abase, bf, w, lane, acc);
    cp_wait<5>(); chunk_mma(CB + 2, 2, abase, bf, w, lane, acc);
    cp_wait<4>(); chunk_mma(CB + 3, 3, abase, bf, w, lane, acc);
    cp_wait<3>(); chunk_mma(CB + 4, 4, abase, bf, w, lane, acc);
    cp_wait<2>(); chunk_mma(CB + 5, 5, abase, bf, w, lane, acc);
    cp_wait<1>(); chunk_mma(CB + 6, 6, abase, bf, w, lane, acc);
    cp_wait<0>(); chunk_mma(CB + 7, 7, abase, bf, w, lane, acc);
}

// ---- main persistent kernel ------------------------------------------------
__global__ void __launch_bounds__(NTHR, 1) lstm_tc(
    const float* __restrict__ hxs, const float* __restrict__ masks,
    const float* __restrict__ W_ih, const float* __restrict__ W_hh,
    const float* __restrict__ b_ih, const float* __restrict__ b_hh,
    float* __restrict__ out)
{
    extern __shared__ __align__(1024) char sm[];
    uint32_t smb = (uint32_t)__cvta_generic_to_shared(sm);
    int tid = threadIdx.x, blk = blockIdx.x, w = tid >> 5, lane = tid & 31;
    int isL0 = (blk < GRP);
    int g = isL0 ? blk : (blk - GRP);
    int l = isL0 ? 0 : 1;
    uint32_t abase = smb + SM_A;
    int u0 = (lane & 3) * 2;               // this thread's unit pair

    // ---- weight conversion: this CTA's 32 gate cols, K=1024, plain fp16 ----
    unsigned short* bw = (unsigned short*)(sm + SM_W);
    for (int idx = tid; idx < 32 * 1024; idx += NTHR) {
        int col = idx >> 10, k = idx & 1023;
        int grow = (col >> 3) * 512 + g * 8 + (col & 7);
        float wv = (k < 512)
            ? W_ih[((size_t)l * 2048 + grow) * 512 + k]
            : W_hh[((size_t)l * 2048 + grow) * 512 + (k - 512)];
        unsigned short hi = __half_as_ushort(__float2half_rn(wv));
        int sg = k >> 4, kk = k & 15;
        int reg = (kk >> 3) & 1, pos = kk & 1;
        int lamd = (col & 7) * 4 + ((kk & 7) >> 1);
        int nt = col >> 3;
        bw[(sg * 4 + nt) * 128 + lamd * 4 + reg * 2 + pos] = hi;
    }

    // ---- bias in registers: [gate nt][unit v] --------------------------------
    float bfr[4][2];
#pragma unroll
    for (int nt = 0; nt < 4; ++nt)
#pragma unroll
        for (int v = 0; v < 2; ++v) {
            int grow = nt * 512 + g * 8 + u0 + v;
            bfr[nt][v] = b_ih[l * 2048 + grow] + b_hh[l * 2048 + grow];
        }

    // ---- init masked h state (pp=0): grid-strided over both layers ---------
    for (int idx = blk * NTHR + tid; idx < 2 * 65536; idx += NBLK * NTHR) {
        int ll = idx >> 16, r = idx & 65535;
        int n = r >> 9, jj = r & 511;
        float v = hxs[(size_t)ll * 131072 + n * 1024 + jj] * __ldg(masks + n);
        stcg16(&g_hst[ll][0][r], __half_as_ushort(__float2half_rn(v)));
    }
    // ---- c-state in registers: [row r][unit v]; rows n = w*32+(lane>>2)+8r --
    float creg[4][2];
#pragma unroll
    for (int r = 0; r < 4; ++r) {
        int n = w * 32 + (lane >> 2) + r * 8;
#pragma unroll
        for (int v = 0; v < 2; ++v)
            creg[r][v] = hxs[(size_t)l * 131072 + n * 1024 + 512 + g * 8 + u0 + v];
    }

    grid_barrier_full();
    const uint2* bf = (const uint2*)(sm + SM_W);

#pragma unroll 1
    for (int t = 0; t < TSTEPS; ++t) {
        int pr = t & 1, pw = pr ^ 1, mb = t & 1;
        float acc[2][4][4] = {};

        if (isL0) {
            half8<0>(g_x + (size_t)t * 65536, abase, bf, w, lane, acc);
            wait_flags(g_flagM, t);
            wait_flags(g_flagL1, t - 1);
            half8<8>(g_hst[0][pr], abase, bf, w, lane, acc);
        } else {
            wait_flags(g_flagL1, t);
            half8<8>(g_hst[1][pr], abase, bf, w, lane, acc);
            wait_flags(g_flagM, t + 1);
            half8<0>(g_mid[mb], abase, bf, w, lane, acc);
        }

        // ---- register epilogue: gates directly from acc fragments -----------
        // acc[mt][nt][q]: row = w*32 + mt*16 + (lane>>2) + (q>=2 ? 8 : 0)
        //                 col = nt*8 + u0 + (q&1)  -> gate nt, unit u0+(q&1)
#pragma unroll
        for (int r = 0; r < 4; ++r) {
            int n = w * 32 + (lane >> 2) + r * 8;
            int mt = r >> 1, qb = (r & 1) * 2;
            float m  = __ldg(masks + t * 128 + n);
            float mn = (t < TSTEPS - 1) ? __ldg(masks + (t + 1) * 128 + n) : 0.f;
            unsigned short sh[2], th[2];
            float hv[2];
#pragma unroll
            for (int v = 0; v < 2; ++v) {
                float zi = acc[mt][0][qb + v] + bfr[0][v];
                float zf = acc[mt][1][qb + v] + bfr[1][v];
                float zg = acc[mt][2][qb + v] + bfr[2][v];
                float zo = acc[mt][3][qb + v] + bfr[3][v];
                float ii = sigm(zi), ff = sigm(zf), oo = sigm(zo);
                float gg = tanhf(zg);
                float cc = ff * (creg[r][v] * m) + ii * gg;
                float hh = oo * tanhf(cc);
                creg[r][v] = cc;
                hv[v] = hh;
                sh[v] = __half_as_ushort(__float2half_rn(hh * mn));
                if (isL0) th[v] = __half_as_ushort(__float2half_rn(hh));
            }
            size_t base = (size_t)n * 512 + g * 8 + u0;
            stcg4(&g_hst[l][pw][base], sh[0] | ((uint32_t)sh[1] << 16));
            if (isL0) {
                stcg4(&g_mid[mb][base], th[0] | ((uint32_t)th[1] << 16));
            } else {
                *(float2*)(out + (size_t)t * 65536 + base) = make_float2(hv[0], hv[1]);
            }
            if (t == TSTEPS - 1) {
                size_t ob = (size_t)OUTN + l * 131072 + n * 1024 + g * 8 + u0;
                *(float2*)(out + ob)       = make_float2(hv[0], hv[1]);
                *(float2*)(out + ob + 512) = make_float2(creg[r][0], creg[r][1]);
            }
        }
        __syncthreads();   // all state writes issued before flag release

        if (tid == 0) {
            __threadfence();
            if (isL0) st_rel(&g_flagM[g],  (unsigned)(t + 1));
            else      st_rel(&g_flagL1[g], (unsigned)(t + 1));
        }
    }
}

// ---- x -> fp16 -------------------------------------------------------------
__global__ void __launch_bounds__(256) xconv(const float* __restrict__ x) {
    size_t i = (size_t)blockIdx.x * 256 + threadIdx.x;
    if (i >= (size_t)OUTN / 4) return;
    float4 v = __ldg(((const float4*)x) + i);
    unsigned short h0 = __half_as_ushort(__float2half_rn(v.x));
    unsigned short h1 = __half_as_ushort(__float2half_rn(v.y));
    unsigned short h2 = __half_as_ushort(__float2half_rn(v.z));
    unsigned short h3 = __half_as_ushort(__float2half_rn(v.w));
    *(uint2*)(g_x + i * 4) = make_uint2(h0 | ((uint32_t)h1 << 16),
                                        h2 | ((uint32_t)h3 << 16));
}

// ---- LayerNorm -------------------------------------------------------------
__global__ void __launch_bounds__(256) ln_kernel(float* __restrict__ out,
                                                 const float* __restrict__ gamma,
                                                 const float* __restrict__ beta)
{
    int lane = threadIdx.x & 31;
    int row  = blockIdx.x * 8 + (threadIdx.x >> 5);
    float* p = out + (size_t)row * 512;
    float4 v[4];
    float s = 0.f, sq = 0.f;
#pragma unroll
    for (int k = 0; k < 4; ++k) {
        v[k] = ((const float4*)p)[(k << 5) + lane];
        s += v[k].x + v[k].y + v[k].z + v[k].w;
        sq = fmaf(v[k].x, v[k].x, sq); sq = fmaf(v[k].y, v[k].y, sq);
        sq = fmaf(v[k].z, v[k].z, sq); sq = fmaf(v[k].w, v[k].w, sq);
    }
#pragma unroll
    for (int o = 16; o; o >>= 1) {
        s  += __shfl_xor_sync(0xffffffffu, s,  o);
        sq += __shfl_xor_sync(0xffffffffu, sq, o);
    }
    float mean = s * (1.0f / 512.0f);
    float inv  = rsqrtf(sq * (1.0f / 512.0f) - mean * mean + 1e-5f);
#pragma unroll
    for (int k = 0; k < 4; ++k) {
        float4 gm = ((const float4*)gamma)[(k << 5) + lane];
        float4 bt = ((const float4*)beta)[(k << 5) + lane];
        float4 r;
        r.x = (v[k].x - mean) * inv * gm.x + bt.x;
        r.y = (v[k].y - mean) * inv * gm.y + bt.y;
        r.z = (v[k].z - mean) * inv * gm.z + bt.z;
        r.w = (v[k].w - mean) * inv * gm.w + bt.w;
        ((float4*)p)[(k << 5) + lane] = r;
    }
}

// ---------------------------------------------------------------------------
extern "C" void kernel_launch(void* const* d_in, const int* in_sizes, int n_in,
                              void* d_out, int out_size) {
    const float* x     = (const float*)d_in[0];
    const float* hxs   = (const float*)d_in[1];
    const float* masks = (const float*)d_in[2];
    const float* W_ih  = (const float*)d_in[3];
    const float* W_hh  = (const float*)d_in[4];
    const float* b_ih  = (const float*)d_in[5];
    const float* b_hh  = (const float*)d_in[6];
    const float* gamma = (const float*)d_in[7];
    const float* beta  = (const float*)d_in[8];
    float* out = (float*)d_out;

    cudaFuncSetAttribute(lstm_tc, cudaFuncAttributeMaxDynamicSharedMemorySize, SM_TOT);

    reset_flags<<<1, 1>>>();
    xconv<<<(OUTN / 4 + 255) / 256, 256>>>(x);
    lstm_tc<<<NBLK, NTHR, SM_TOT>>>(hxs, masks, W_ih, W_hh, b_ih, b_hh, out);
    ln_kernel<<<65536 / 8, 256>>>(out, gamma, beta);
}